// round 16
// baseline (speedup 1.0000x reference)
#include <cuda_runtime.h>
#include <cstdint>
#include <math.h>

#define NB     32
#define NH     32
#define NHKV   8
#define NG     4
#define ND     128
#define NPG    32
#define PS     128
#define NPAGES 1024
#define NUNITS (NPAGES * NHKV * 2)     // 16384 half-page units, physical order
#define NHP    64                      // partials per (b,qhead): lp*2+hf
#define TILE_F 8192                    // floats per half tile (64 x 128)
#define TILE_B 32768u
#define SCALE  0.08838834764831845f    // 1/sqrt(128)

// -------- device scratch (static: allocation-free) --------
__device__ float g_Pm[NB * NH * NHP];                           // partial max
__device__ float g_Pl[NB * NH * NHP];                           // partial expsum
__device__ float g_Pacc[(size_t)NB * NH * NHP * ND];            // partial P*V (33.5 MB)

// ---------------- PTX helpers ----------------
__device__ __forceinline__ void mbar_init(uint32_t a, int cnt) {
    asm volatile("mbarrier.init.shared.b64 [%0], %1;" :: "r"(a), "r"(cnt) : "memory");
}
__device__ __forceinline__ void mbar_expect(uint32_t a, uint32_t bytes) {
    asm volatile("mbarrier.arrive.expect_tx.shared.b64 _, [%0], %1;"
                 :: "r"(a), "r"(bytes) : "memory");
}
__device__ __forceinline__ void mbar_wait(uint32_t a, int parity) {
    asm volatile(
        "{\n\t.reg .pred P;\n\t"
        "W%=:\n\t"
        "mbarrier.try_wait.parity.acquire.cta.shared::cta.b64 P, [%0], %1, 0x989680;\n\t"
        "@P bra.uni D%=;\n\t"
        "bra.uni W%=;\n\t"
        "D%=:\n\t}"
        :: "r"(a), "r"(parity) : "memory");
}
__device__ __forceinline__ void bulk_ld(uint32_t dst, const void* src, uint32_t bytes, uint32_t mbar) {
    asm volatile("cp.async.bulk.shared::cta.global.mbarrier::complete_tx::bytes [%0], [%1], %2, [%3];"
                 :: "r"(dst), "l"(src), "r"(bytes), "r"(mbar) : "memory");
}
__device__ __forceinline__ void bulk_st(void* dst, uint32_t src, uint32_t bytes) {
    asm volatile("cp.async.bulk.global.shared::cta.bulk_group [%0], [%1], %2;"
                 :: "l"(dst), "r"(src), "r"(bytes) : "memory");
}

// ---------------------------------------------------------------------------
// Persistent fused update+copy+attend (proven hot loop — unchanged).
__global__ void __launch_bounds__(512, 1)
fused_kernel(const float* __restrict__ q,
             const float* __restrict__ knew,
             const float* __restrict__ vnew,
             const float* __restrict__ kc,
             const float* __restrict__ vc,
             const int*   __restrict__ pos_,
             const int*   __restrict__ pt,
             float* __restrict__ ok,
             float* __restrict__ ov)
{
    extern __shared__ __align__(128) float smf[];
    // layout: K tiles [3][8192] | V tiles [3][8192] | qs[512] | sp[256] |
    //         mbars(16f) | sinv[1024] | spos[32] | supd[32]
    float* qs = smf + 6 * TILE_F;
    float* sp = qs + 512;
    const uint32_t smbase = (uint32_t)__cvta_generic_to_shared(smf);
    const uint32_t mb0 = (uint32_t)__cvta_generic_to_shared(sp + 256);
    int*  sinv = (int*)(sp + 256 + 16);
    int*  spos = sinv + 1024;
    int*  supd = spos + 32;

    const int t = threadIdx.x;
    const int w = t >> 5, lane = t & 31;
    const int grid = gridDim.x;

    if (t == 0) {
#pragma unroll
        for (int i = 0; i < 3; i++) mbar_init(mb0 + 8 * i, 1);
    }

    int u = blockIdx.x;
    // prologue prefetch (pure physical address, needs no metadata)
    if (t == 0 && u < NUNITS) {
        mbar_expect(mb0, 2 * TILE_B);
        bulk_ld(smbase,              kc + (size_t)u * TILE_F, TILE_B, mb0);
        bulk_ld(smbase + 3 * TILE_B, vc + (size_t)u * TILE_F, TILE_B, mb0);
    }

    // local metadata tables (4 KB inverse page table + pos + update page)
    for (int i = t; i < NPAGES; i += 512) sinv[pt[i]] = i;
    if (t < NB) {
        int p = pos_[t];
        spos[t] = p;
        supd[t] = pt[t * NPG + (p >> 7)];
    }
    __syncthreads();

    int it = 0;
    for (; u < NUNITS; u += grid, ++it) {
        const int s = it % 3;
        float* kb = smf + s * TILE_F;
        float* vb = smf + (3 + s) * TILE_F;

        __syncthreads();   // prev iter's reads of all buffers done

        // ---- prefetch next unit (stage s+1; its store group is >=2 old) ----
        const int un = u + grid;
        if (t == 0 && un < NUNITS) {
            const int sn = (s + 1) % 3;
            asm volatile("cp.async.bulk.wait_group.read 1;" ::: "memory");
            mbar_expect(mb0 + 8 * sn, 2 * TILE_B);
            bulk_ld(smbase + sn * TILE_B,       kc + (size_t)un * TILE_F, TILE_B, mb0 + 8 * sn);
            bulk_ld(smbase + (3 + sn) * TILE_B, vc + (size_t)un * TILE_F, TILE_B, mb0 + 8 * sn);
        }

        // ---- unit metadata (SMEM tables) ----
        const int pp = u >> 4, h = (u >> 1) & 7, hf = u & 1;
        const int owner = sinv[pp];
        const int b = owner >> 5, lp = owner & 31;
        const int pos = spos[b];
        const int startrow = lp * PS + hf * 64;
        const bool do_attn = startrow <= pos;
        const int nvalid = min(64, pos - startrow + 1);
        const int slot = pos & 127;
        const bool has_upd = (pp == supd[b]) && ((slot >> 6) == hf);
        const size_t base = (size_t)u * TILE_F;

        // ---- wait current tiles ----
        mbar_wait(mb0 + 8 * s, (it / 3) & 1);

        // q load + new-token patch into SMEM (pre-store & pre-compute)
        if (do_attn) qs[t] = q[((size_t)b * NH + h * NG) * ND + t];
        if (has_upd) {
            const int r = slot & 63;
            if (t < 32)
                ((float4*)(kb + r * ND))[t] =
                    ((const float4*)(knew + ((size_t)b * NHKV + h) * ND))[t];
            else if (t < 64)
                ((float4*)(vb + r * ND))[t - 32] =
                    ((const float4*)(vnew + ((size_t)b * NHKV + h) * ND))[t - 32];
        }
        __syncthreads();

        // ---- async bulk store of (patched) tiles ----
        if (t == 0) {
            asm volatile("fence.proxy.async.shared::cta;" ::: "memory");
            bulk_st(ok + base, smbase + s * TILE_B,       TILE_B);
            bulk_st(ov + base, smbase + (3 + s) * TILE_B, TILE_B);
            asm volatile("cp.async.bulk.commit_group;" ::: "memory");
        }

        if (do_attn) {
            // ---- QK: warp w rows {w, w+16, w+32, w+48}; float4 + shuffle ----
            const float4 q0 = ((const float4*)qs)[lane];
            const float4 q1 = ((const float4*)qs)[32 + lane];
            const float4 q2 = ((const float4*)qs)[64 + lane];
            const float4 q3 = ((const float4*)qs)[96 + lane];
            for (int r = w; r < 64; r += 16) {
                float4 kv = ((const float4*)(kb + r * ND))[lane];
                float s0 = kv.x*q0.x + kv.y*q0.y + kv.z*q0.z + kv.w*q0.w;
                float s1 = kv.x*q1.x + kv.y*q1.y + kv.z*q1.z + kv.w*q1.w;
                float s2 = kv.x*q2.x + kv.y*q2.y + kv.z*q2.z + kv.w*q2.w;
                float s3 = kv.x*q3.x + kv.y*q3.y + kv.z*q3.z + kv.w*q3.w;
#pragma unroll
                for (int off = 16; off; off >>= 1) {
                    s0 += __shfl_xor_sync(0xffffffffu, s0, off);
                    s1 += __shfl_xor_sync(0xffffffffu, s1, off);
                    s2 += __shfl_xor_sync(0xffffffffu, s2, off);
                    s3 += __shfl_xor_sync(0xffffffffu, s3, off);
                }
                if (lane == 0) {
                    bool val = r < nvalid;
                    sp[r]       = val ? s0 * SCALE : -INFINITY;
                    sp[64 + r]  = val ? s1 * SCALE : -INFINITY;
                    sp[128 + r] = val ? s2 * SCALE : -INFINITY;
                    sp[192 + r] = val ? s3 * SCALE : -INFINITY;
                }
            }
            __syncthreads();

            // ---- partial softmax: warp g reduces its 64 scores ----
            if (w < NG) {
                float2 v2 = ((const float2*)(sp + w * 64))[lane];
                float m = fmaxf(v2.x, v2.y);
#pragma unroll
                for (int off = 16; off; off >>= 1)
                    m = fmaxf(m, __shfl_xor_sync(0xffffffffu, m, off));
                float ex = __expf(v2.x - m), ey = __expf(v2.y - m);
                float l = ex + ey;
#pragma unroll
                for (int off = 16; off; off >>= 1)
                    l += __shfl_xor_sync(0xffffffffu, l, off);
                ((float2*)(sp + w * 64))[lane] = make_float2(ex, ey);
                if (lane == 0) {
                    int id = (b * NH + h * NG + w) * NHP + lp * 2 + hf;
                    g_Pm[id] = m;
                    g_Pl[id] = l;
                }
            }
            __syncthreads();

            // ---- P*V: thread t -> (qh = t>>7, d = t&127), dual accumulators ----
            const int qh = t >> 7, d = t & 127;
            const float* spq = sp + qh * 64;
            float a0 = 0.f, a1 = 0.f;
            int r = 0;
            for (; r + 1 < nvalid; r += 2) {
                a0 = fmaf(spq[r],     vb[r * ND + d],       a0);
                a1 = fmaf(spq[r + 1], vb[(r + 1) * ND + d], a1);
            }
            if (r < nvalid) a0 = fmaf(spq[r], vb[r * ND + d], a0);
            g_Pacc[(size_t)((b * NH + h * NG + qh) * NHP + lp * 2 + hf) * ND + d] = a0 + a1;
        }
    }

    // drain outstanding bulk stores (SMEM safety + GMEM visibility)
    if (t == 0) asm volatile("cp.async.bulk.wait_group 0;" ::: "memory");
}

// ---------------------------------------------------------------------------
// Parallel split-softmax combine, 512 threads per (b, q-head) block.
// Thread = (grp = t>>7, d = t&127). Group grp accumulates hp = grp, grp+4, ...
// -> 4x memory parallelism vs 128-thread version; cross-group sum via SMEM.
__global__ void __launch_bounds__(512, 2)
reduce_kernel(const int* __restrict__ pos_, float* __restrict__ out)
{
    __shared__ float sc[NHP];            // coefficients c[hp]
    __shared__ float red[8];             // phase-1 cross-warp scratch
    __shared__ float spart[4][ND];       // cross-group partial sums
    __shared__ float sL;

    const int uu = blockIdx.x;           // b*32 + h*4 + g
    const int b = uu >> 5;
    const int t = threadIdx.x;
    const int w = t >> 5, lane = t & 31;
    const int grp = t >> 7, d = t & 127;
    const int nhp = (pos_[b] >> 6) + 1;  // 1..64 valid partials

    // ---- phase 1: parallel coefficients (warps 0-3 cover 128 lanes >= NHP) ----
    if (t < 128) {
        float m = -INFINITY, l = 0.f;
        if (t < nhp) { m = g_Pm[uu * NHP + t]; l = g_Pl[uu * NHP + t]; }

        float M = m;
#pragma unroll
        for (int off = 16; off; off >>= 1)
            M = fmaxf(M, __shfl_xor_sync(0xffffffffu, M, off));
        if (lane == 0) red[w] = M;
        __syncwarp();
    }
    __syncthreads();
    const float M = fmaxf(fmaxf(red[0], red[1]), fmaxf(red[2], red[3]));
    if (t < 128) {
        const float c = (t < nhp) ? __expf(g_Pm[uu * NHP + t] - M) : 0.f;
        if (t < NHP) sc[t] = c;
        float cl = c * ((t < nhp) ? g_Pl[uu * NHP + t] : 0.f);
#pragma unroll
        for (int off = 16; off; off >>= 1)
            cl += __shfl_xor_sync(0xffffffffu, cl, off);
        if (lane == 0) red[4 + w] = cl;
    }
    __syncthreads();
    if (t == 0) sL = red[4] + red[5] + red[6] + red[7];

    // ---- phase 2: group grp sums hp = grp, grp+4, ... (interleaved rows) ----
    const float* pa = g_Pacc + (size_t)uu * NHP * ND + d;
    float O = 0.f;
    int hp = grp;
    // up to 16 iterations; unroll-by-4 over the strided sequence
    for (; hp + 12 < nhp; hp += 16) {
        float v0 = pa[(size_t)hp * ND];
        float v1 = pa[(size_t)(hp + 4) * ND];
        float v2 = pa[(size_t)(hp + 8) * ND];
        float v3 = pa[(size_t)(hp + 12) * ND];
        O = fmaf(v0, sc[hp],      O);
        O = fmaf(v1, sc[hp + 4],  O);
        O = fmaf(v2, sc[hp + 8],  O);
        O = fmaf(v3, sc[hp + 12], O);
    }
    for (; hp < nhp; hp += 4)
        O = fmaf(pa[(size_t)hp * ND], sc[hp], O);
    spart[grp][d] = O;
    __syncthreads();

    if (t < ND) {
        const float Osum = spart[0][t] + spart[1][t] + spart[2][t] + spart[3][t];
        out[(size_t)uu * ND + t] = Osum / sL;
    }
}

// ---------------------------------------------------------------------------
extern "C" void kernel_launch(void* const* d_in, const int* in_sizes, int n_in,
                              void* d_out, int out_size)
{
    const float* q   = (const float*)d_in[0];
    const float* kn  = (const float*)d_in[1];
    const float* vn  = (const float*)d_in[2];
    const float* kc  = (const float*)d_in[3];
    const float* vc  = (const float*)d_in[4];
    const int*   pos = (const int*)d_in[5];
    const int*   pt  = (const int*)d_in[6];

    float* out_attn = (float*)d_out;
    float* out_k    = out_attn + (size_t)NB * NH * ND;             // +131072
    float* out_v    = out_k + (size_t)NPAGES * NHKV * PS * ND;     // +134217728

    int nsm = 148;
    if (cudaDeviceGetAttribute(&nsm, cudaDevAttrMultiProcessorCount, 0) != cudaSuccess || nsm <= 0)
        nsm = 148;

    // 6 tiles*32KB + qs 2KB + sp 1KB + mbars 64B + sinv 4KB + spos/supd 256B
    const int smem = (6 * TILE_F + 512 + 256 + 16 + 1024 + 64) * (int)sizeof(float); // 204128 B
    cudaFuncSetAttribute(fused_kernel, cudaFuncAttributeMaxDynamicSharedMemorySize, smem);

    fused_kernel<<<nsm, 512, smem>>>(q, kn, vn, kc, vc, pos, pt, out_k, out_v);
    reduce_kernel<<<NB * NH, 512>>>(pos, out_attn);
}

// round 17
// speedup vs baseline: 1.0068x; 1.0068x over previous
#include <cuda_runtime.h>
#include <cstdint>
#include <math.h>

#define NB     32
#define NH     32
#define NHKV   8
#define NG     4
#define ND     128
#define NPG    32
#define PS     128
#define NPAGES 1024
#define NUNITS (NPAGES * NHKV * 2)     // 16384 half-page units, physical order
#define NHP    64                      // partials per (b,qhead): lp*2+hf
#define TILE_F 8192                    // floats per half tile (64 x 128)
#define TILE_B 32768u
#define SCALE  0.08838834764831845f    // 1/sqrt(128)

// -------- device scratch (static: allocation-free) --------
__device__ float g_Pm[NB * NH * NHP];                           // partial max
__device__ float g_Pl[NB * NH * NHP];                           // partial expsum
__device__ float g_Pacc[(size_t)NB * NH * NHP * ND];            // partial P*V (33.5 MB)

// ---------------- PTX helpers ----------------
__device__ __forceinline__ void mbar_init(uint32_t a, int cnt) {
    asm volatile("mbarrier.init.shared.b64 [%0], %1;" :: "r"(a), "r"(cnt) : "memory");
}
__device__ __forceinline__ void mbar_expect(uint32_t a, uint32_t bytes) {
    asm volatile("mbarrier.arrive.expect_tx.shared.b64 _, [%0], %1;"
                 :: "r"(a), "r"(bytes) : "memory");
}
__device__ __forceinline__ void mbar_wait(uint32_t a, int parity) {
    asm volatile(
        "{\n\t.reg .pred P;\n\t"
        "W%=:\n\t"
        "mbarrier.try_wait.parity.acquire.cta.shared::cta.b64 P, [%0], %1, 0x989680;\n\t"
        "@P bra.uni D%=;\n\t"
        "bra.uni W%=;\n\t"
        "D%=:\n\t}"
        :: "r"(a), "r"(parity) : "memory");
}
__device__ __forceinline__ void bulk_ld(uint32_t dst, const void* src, uint32_t bytes, uint32_t mbar) {
    asm volatile("cp.async.bulk.shared::cta.global.mbarrier::complete_tx::bytes [%0], [%1], %2, [%3];"
                 :: "r"(dst), "l"(src), "r"(bytes), "r"(mbar) : "memory");
}
__device__ __forceinline__ void bulk_st(void* dst, uint32_t src, uint32_t bytes) {
    asm volatile("cp.async.bulk.global.shared::cta.bulk_group [%0], [%1], %2;"
                 :: "l"(dst), "r"(src), "r"(bytes) : "memory");
}

// ---------------------------------------------------------------------------
// Persistent fused update+copy+attend (proven hot loop — unchanged).
__global__ void __launch_bounds__(512, 1)
fused_kernel(const float* __restrict__ q,
             const float* __restrict__ knew,
             const float* __restrict__ vnew,
             const float* __restrict__ kc,
             const float* __restrict__ vc,
             const int*   __restrict__ pos_,
             const int*   __restrict__ pt,
             float* __restrict__ ok,
             float* __restrict__ ov)
{
    extern __shared__ __align__(128) float smf[];
    // layout: K tiles [3][8192] | V tiles [3][8192] | qs[512] | sp[256] |
    //         mbars(16f) | sinv[1024] | spos[32] | supd[32]
    float* qs = smf + 6 * TILE_F;
    float* sp = qs + 512;
    const uint32_t smbase = (uint32_t)__cvta_generic_to_shared(smf);
    const uint32_t mb0 = (uint32_t)__cvta_generic_to_shared(sp + 256);
    int*  sinv = (int*)(sp + 256 + 16);
    int*  spos = sinv + 1024;
    int*  supd = spos + 32;

    const int t = threadIdx.x;
    const int w = t >> 5, lane = t & 31;
    const int grid = gridDim.x;

    if (t == 0) {
#pragma unroll
        for (int i = 0; i < 3; i++) mbar_init(mb0 + 8 * i, 1);
    }

    int u = blockIdx.x;
    // prologue prefetch (pure physical address, needs no metadata)
    if (t == 0 && u < NUNITS) {
        mbar_expect(mb0, 2 * TILE_B);
        bulk_ld(smbase,              kc + (size_t)u * TILE_F, TILE_B, mb0);
        bulk_ld(smbase + 3 * TILE_B, vc + (size_t)u * TILE_F, TILE_B, mb0);
    }

    // local metadata tables (4 KB inverse page table + pos + update page)
    for (int i = t; i < NPAGES; i += 512) sinv[pt[i]] = i;
    if (t < NB) {
        int p = pos_[t];
        spos[t] = p;
        supd[t] = pt[t * NPG + (p >> 7)];
    }
    __syncthreads();

    int it = 0;
    for (; u < NUNITS; u += grid, ++it) {
        const int s = it % 3;
        float* kb = smf + s * TILE_F;
        float* vb = smf + (3 + s) * TILE_F;

        __syncthreads();   // prev iter's reads of all buffers done

        // ---- prefetch next unit (stage s+1; its store group is >=2 old) ----
        const int un = u + grid;
        if (t == 0 && un < NUNITS) {
            const int sn = (s + 1) % 3;
            asm volatile("cp.async.bulk.wait_group.read 1;" ::: "memory");
            mbar_expect(mb0 + 8 * sn, 2 * TILE_B);
            bulk_ld(smbase + sn * TILE_B,       kc + (size_t)un * TILE_F, TILE_B, mb0 + 8 * sn);
            bulk_ld(smbase + (3 + sn) * TILE_B, vc + (size_t)un * TILE_F, TILE_B, mb0 + 8 * sn);
        }

        // ---- unit metadata (SMEM tables) ----
        const int pp = u >> 4, h = (u >> 1) & 7, hf = u & 1;
        const int owner = sinv[pp];
        const int b = owner >> 5, lp = owner & 31;
        const int pos = spos[b];
        const int startrow = lp * PS + hf * 64;
        const bool do_attn = startrow <= pos;
        const int nvalid = min(64, pos - startrow + 1);
        const int slot = pos & 127;
        const bool has_upd = (pp == supd[b]) && ((slot >> 6) == hf);
        const size_t base = (size_t)u * TILE_F;

        // ---- wait current tiles ----
        mbar_wait(mb0 + 8 * s, (it / 3) & 1);

        // q load + new-token patch into SMEM (pre-store & pre-compute)
        if (do_attn) qs[t] = q[((size_t)b * NH + h * NG) * ND + t];
        if (has_upd) {
            const int r = slot & 63;
            if (t < 32)
                ((float4*)(kb + r * ND))[t] =
                    ((const float4*)(knew + ((size_t)b * NHKV + h) * ND))[t];
            else if (t < 64)
                ((float4*)(vb + r * ND))[t - 32] =
                    ((const float4*)(vnew + ((size_t)b * NHKV + h) * ND))[t - 32];
        }
        __syncthreads();

        // ---- async bulk store of (patched) tiles ----
        if (t == 0) {
            asm volatile("fence.proxy.async.shared::cta;" ::: "memory");
            bulk_st(ok + base, smbase + s * TILE_B,       TILE_B);
            bulk_st(ov + base, smbase + (3 + s) * TILE_B, TILE_B);
            asm volatile("cp.async.bulk.commit_group;" ::: "memory");
        }

        if (do_attn) {
            // ---- QK: warp w rows {w, w+16, w+32, w+48}; float4 + shuffle ----
            const float4 q0 = ((const float4*)qs)[lane];
            const float4 q1 = ((const float4*)qs)[32 + lane];
            const float4 q2 = ((const float4*)qs)[64 + lane];
            const float4 q3 = ((const float4*)qs)[96 + lane];
            for (int r = w; r < 64; r += 16) {
                float4 kv = ((const float4*)(kb + r * ND))[lane];
                float s0 = kv.x*q0.x + kv.y*q0.y + kv.z*q0.z + kv.w*q0.w;
                float s1 = kv.x*q1.x + kv.y*q1.y + kv.z*q1.z + kv.w*q1.w;
                float s2 = kv.x*q2.x + kv.y*q2.y + kv.z*q2.z + kv.w*q2.w;
                float s3 = kv.x*q3.x + kv.y*q3.y + kv.z*q3.z + kv.w*q3.w;
#pragma unroll
                for (int off = 16; off; off >>= 1) {
                    s0 += __shfl_xor_sync(0xffffffffu, s0, off);
                    s1 += __shfl_xor_sync(0xffffffffu, s1, off);
                    s2 += __shfl_xor_sync(0xffffffffu, s2, off);
                    s3 += __shfl_xor_sync(0xffffffffu, s3, off);
                }
                if (lane == 0) {
                    bool val = r < nvalid;
                    sp[r]       = val ? s0 * SCALE : -INFINITY;
                    sp[64 + r]  = val ? s1 * SCALE : -INFINITY;
                    sp[128 + r] = val ? s2 * SCALE : -INFINITY;
                    sp[192 + r] = val ? s3 * SCALE : -INFINITY;
                }
            }
            __syncthreads();

            // ---- partial softmax: warp g reduces its 64 scores ----
            if (w < NG) {
                float2 v2 = ((const float2*)(sp + w * 64))[lane];
                float m = fmaxf(v2.x, v2.y);
#pragma unroll
                for (int off = 16; off; off >>= 1)
                    m = fmaxf(m, __shfl_xor_sync(0xffffffffu, m, off));
                float ex = __expf(v2.x - m), ey = __expf(v2.y - m);
                float l = ex + ey;
#pragma unroll
                for (int off = 16; off; off >>= 1)
                    l += __shfl_xor_sync(0xffffffffu, l, off);
                ((float2*)(sp + w * 64))[lane] = make_float2(ex, ey);
                if (lane == 0) {
                    int id = (b * NH + h * NG + w) * NHP + lp * 2 + hf;
                    g_Pm[id] = m;
                    g_Pl[id] = l;
                }
            }
            __syncthreads();

            // ---- P*V: thread t -> (qh = t>>7, d = t&127), dual accumulators ----
            const int qh = t >> 7, d = t & 127;
            const float* spq = sp + qh * 64;
            float a0 = 0.f, a1 = 0.f;
            int r = 0;
            for (; r + 1 < nvalid; r += 2) {
                a0 = fmaf(spq[r],     vb[r * ND + d],       a0);
                a1 = fmaf(spq[r + 1], vb[(r + 1) * ND + d], a1);
            }
            if (r < nvalid) a0 = fmaf(spq[r], vb[r * ND + d], a0);
            g_Pacc[(size_t)((b * NH + h * NG + qh) * NHP + lp * 2 + hf) * ND + d] = a0 + a1;
        }
    }

    // drain outstanding bulk stores (SMEM safety + GMEM visibility)
    if (t == 0) asm volatile("cp.async.bulk.wait_group 0;" ::: "memory");
}

// ---------------------------------------------------------------------------
// Parallel split-softmax combine. One block per (b, q-head), 128 threads.
// Phase 1: all (m,l) partials loaded/exp'd in parallel -> coefficients in SMEM.
// Phase 2: warp w owns rows hp = w, w+4, ... ; each lane loads a float4 so a
// warp covers one full 512B row per LDG.128 round. float4 accumulator, 4-deep
// unroll -> 4 independent 16B loads in flight per thread. Cross-warp sum in
// SMEM; warp 0 writes the result as float4.
__global__ void __launch_bounds__(128, 8)
reduce_kernel(const int* __restrict__ pos_, float* __restrict__ out)
{
    __shared__ float sc[NHP];            // coefficients c[hp]
    __shared__ float red[8];             // cross-warp scratch (max / sum)
    __shared__ float4 spart[4][32];      // cross-warp float4 partials

    const int uu = blockIdx.x;           // b*32 + h*4 + g
    const int b = uu >> 5;
    const int t = threadIdx.x;
    const int w = t >> 5, lane = t & 31;
    const int nhp = (pos_[b] >> 6) + 1;  // 1..64 valid partials

    // ---- phase 1: parallel coefficients ----
    float m = -INFINITY, l = 0.f;
    if (t < nhp) { m = g_Pm[uu * NHP + t]; l = g_Pl[uu * NHP + t]; }

    float M = m;
#pragma unroll
    for (int off = 16; off; off >>= 1)
        M = fmaxf(M, __shfl_xor_sync(0xffffffffu, M, off));
    if (lane == 0) red[w] = M;
    __syncthreads();
    M = fmaxf(fmaxf(red[0], red[1]), fmaxf(red[2], red[3]));

    const float c = (t < nhp) ? __expf(m - M) : 0.f;
    if (t < NHP) sc[t] = c;

    float cl = c * l;
#pragma unroll
    for (int off = 16; off; off >>= 1)
        cl += __shfl_xor_sync(0xffffffffu, cl, off);
    if (lane == 0) red[4 + w] = cl;
    __syncthreads();
    const float L = red[4] + red[5] + red[6] + red[7];

    // ---- phase 2: warp w sums rows hp = w, w+4, ... with float4 loads ----
    const float4* pa4 = (const float4*)(g_Pacc + (size_t)uu * NHP * ND) + lane;
    float4 O = make_float4(0.f, 0.f, 0.f, 0.f);
    int hp = w;
    for (; hp + 12 < nhp; hp += 16) {
        float4 v0 = pa4[(hp)      * 32];
        float4 v1 = pa4[(hp + 4)  * 32];
        float4 v2 = pa4[(hp + 8)  * 32];
        float4 v3 = pa4[(hp + 12) * 32];
        float c0 = sc[hp], c1 = sc[hp + 4], c2 = sc[hp + 8], c3 = sc[hp + 12];
        O.x = fmaf(v0.x, c0, O.x); O.y = fmaf(v0.y, c0, O.y);
        O.z = fmaf(v0.z, c0, O.z); O.w = fmaf(v0.w, c0, O.w);
        O.x = fmaf(v1.x, c1, O.x); O.y = fmaf(v1.y, c1, O.y);
        O.z = fmaf(v1.z, c1, O.z); O.w = fmaf(v1.w, c1, O.w);
        O.x = fmaf(v2.x, c2, O.x); O.y = fmaf(v2.y, c2, O.y);
        O.z = fmaf(v2.z, c2, O.z); O.w = fmaf(v2.w, c2, O.w);
        O.x = fmaf(v3.x, c3, O.x); O.y = fmaf(v3.y, c3, O.y);
        O.z = fmaf(v3.z, c3, O.z); O.w = fmaf(v3.w, c3, O.w);
    }
    for (; hp < nhp; hp += 4) {
        float4 v = pa4[hp * 32];
        float cc = sc[hp];
        O.x = fmaf(v.x, cc, O.x); O.y = fmaf(v.y, cc, O.y);
        O.z = fmaf(v.z, cc, O.z); O.w = fmaf(v.w, cc, O.w);
    }
    spart[w][lane] = O;
    __syncthreads();

    // ---- final: warp 0 combines 4 warps' partials and writes float4 ----
    if (w == 0) {
        float4 a = spart[0][lane], b4 = spart[1][lane],
               cc = spart[2][lane], dd = spart[3][lane];
        float inv = 1.0f / L;
        float4 r;
        r.x = (a.x + b4.x + cc.x + dd.x) * inv;
        r.y = (a.y + b4.y + cc.y + dd.y) * inv;
        r.z = (a.z + b4.z + cc.z + dd.z) * inv;
        r.w = (a.w + b4.w + cc.w + dd.w) * inv;
        ((float4*)(out + (size_t)uu * ND))[lane] = r;
    }
}

// ---------------------------------------------------------------------------
extern "C" void kernel_launch(void* const* d_in, const int* in_sizes, int n_in,
                              void* d_out, int out_size)
{
    const float* q   = (const float*)d_in[0];
    const float* kn  = (const float*)d_in[1];
    const float* vn  = (const float*)d_in[2];
    const float* kc  = (const float*)d_in[3];
    const float* vc  = (const float*)d_in[4];
    const int*   pos = (const int*)d_in[5];
    const int*   pt  = (const int*)d_in[6];

    float* out_attn = (float*)d_out;
    float* out_k    = out_attn + (size_t)NB * NH * ND;             // +131072
    float* out_v    = out_k + (size_t)NPAGES * NHKV * PS * ND;     // +134217728

    int nsm = 148;
    if (cudaDeviceGetAttribute(&nsm, cudaDevAttrMultiProcessorCount, 0) != cudaSuccess || nsm <= 0)
        nsm = 148;

    // 6 tiles*32KB + qs 2KB + sp 1KB + mbars 64B + sinv 4KB + spos/supd 256B
    const int smem = (6 * TILE_F + 512 + 256 + 16 + 1024 + 64) * (int)sizeof(float); // 204128 B
    cudaFuncSetAttribute(fused_kernel, cudaFuncAttributeMaxDynamicSharedMemorySize, smem);

    fused_kernel<<<nsm, 512, smem>>>(q, kn, vn, kc, vc, pos, pt, out_k, out_v);
    reduce_kernel<<<NB * NH, 128>>>(pos, out_attn);
}